// round 13
// baseline (speedup 1.0000x reference)
#include <cuda_runtime.h>
#include <cuda_bf16.h>
#include <stdint.h>
#include <math.h>

// ---------------- problem constants ----------------
#define DMODEL 1024
#define DINNER 2048
#define DSTATE 16
#define DCONV  4
#define DTRANK 64
#define BB     2
#define LL     2048
#define ROWS   (BB*LL)            // 4096
#define NCHUNK 16
#define LC     (LL/NCHUNK)        // 128
#define L2E    1.4426950408889634f
#define NPROJ  (DTRANK + 2*DSTATE) // 96

// ---------------- scratch (device globals; no allocations allowed) ----------------
__device__ __nv_bfloat16 g_xbf   [ROWS*DMODEL];
__device__ __nv_bfloat16 g_Winbf [DMODEL*2*DINNER];
__device__ float         g_xz    [(size_t)ROWS*2*DINNER];   // xs cols [0,2048), z cols [2048,4096)
__device__ float         g_xc    [(size_t)ROWS*DINNER];
__device__ __nv_bfloat16 g_xcbf  [(size_t)ROWS*DINNER];
__device__ __nv_bfloat16 g_Wxpbf [DINNER*NPROJ];
__device__ float         g_proj  [(size_t)ROWS*NPROJ];      // dt_r [0,64), B [64,80), C [80,96)
__device__ __nv_bfloat16 g_dtrbf [(size_t)ROWS*DTRANK];
__device__ __nv_bfloat16 g_Wdtbf [DTRANK*DINNER];
__device__ float         g_dt    [(size_t)ROWS*DINNER];
__device__ float         g_ylocal[(size_t)ROWS*DINNER];
__device__ float         g_hend  [(size_t)BB*DINNER*NCHUNK*DSTATE];
__device__ float         g_hin   [(size_t)BB*DINNER*NCHUNK*DSTATE];
__device__ float         g_dtsum [(size_t)BB*DINNER*NCHUNK];
__device__ __nv_bfloat16 g_ybf   [(size_t)ROWS*DINNER];
__device__ __nv_bfloat16 g_Woutbf[DINNER*DMODEL];
__device__ float         g_out   [(size_t)ROWS*DMODEL];

// ---------------- helpers ----------------
__global__ void k_f2b(const float* __restrict__ s, __nv_bfloat16* __restrict__ d, int n) {
    int i = blockIdx.x*256 + threadIdx.x;
    int st = gridDim.x*256;
    for (; i < n; i += st) d[i] = __float2bfloat16(s[i]);
}

// ---------------- bf16 mma GEMM: C[M,N] = A[M,K] * B[K,N] (all row-major, fp32 accum) ----
#define GBM 128
#define GBN 128
#define GBK 32
#define GLD 40   // smem leading dim (bf16 elems); keeps uint4 stores 16B aligned

__global__ __launch_bounds__(256)
void k_gemm(const __nv_bfloat16* __restrict__ A,
            const __nv_bfloat16* __restrict__ B,
            float* __restrict__ C,
            int M, int N, int K)
{
    __shared__ __nv_bfloat16 As[GBM*GLD];
    __shared__ __nv_bfloat16 Bs[GBN*GLD];   // stored transposed: Bs[n][k]

    const int tid  = threadIdx.x;
    const int lane = tid & 31, wid = tid >> 5;
    const int wr = wid >> 1, wc = wid & 1;       // warp 4x2 grid -> warp tile 32x64
    const int grp = lane >> 2, tig = lane & 3;
    const int bm = blockIdx.y * GBM, bn = blockIdx.x * GBN;

    float acc[2][8][4];
#pragma unroll
    for (int a = 0; a < 2; a++)
#pragma unroll
        for (int b = 0; b < 8; b++)
#pragma unroll
            for (int c = 0; c < 4; c++) acc[a][b][c] = 0.f;

    for (int kt = 0; kt < K; kt += GBK) {
        // load A tile 128x32 (2 uint4 per thread)
#pragma unroll
        for (int it = 0; it < 2; it++) {
            int idx = tid + it*256;
            int r  = idx >> 2;
            int c8 = (idx & 3) << 3;
            uint4 v = *reinterpret_cast<const uint4*>(A + (size_t)(bm + r)*K + kt + c8);
            *reinterpret_cast<uint4*>(&As[r*GLD + c8]) = v;
        }
        // load B tile 32x128 and transpose into Bs[n][k]
#pragma unroll
        for (int it = 0; it < 2; it++) {
            int idx = tid + it*256;
            int kk = idx >> 4;
            int n0 = (idx & 15) << 3;
            int gn = bn + n0;
            __align__(16) __nv_bfloat16 t8[8];
            if (gn + 8 <= N) {
                *reinterpret_cast<uint4*>(t8) =
                    *reinterpret_cast<const uint4*>(B + (size_t)(kt + kk)*N + gn);
            } else {
#pragma unroll
                for (int j = 0; j < 8; j++)
                    t8[j] = (gn + j < N) ? B[(size_t)(kt + kk)*N + gn + j]
                                         : __float2bfloat16(0.f);
            }
#pragma unroll
            for (int j = 0; j < 8; j++) Bs[(n0 + j)*GLD + kk] = t8[j];
        }
        __syncthreads();

#pragma unroll
        for (int ks = 0; ks < 2; ks++) {
            const int k0 = ks*16 + tig*2;
            uint32_t af[2][4], bfr[8][2];
#pragma unroll
            for (int mi = 0; mi < 2; mi++) {
                int r = wr*32 + mi*16 + grp;
                af[mi][0] = *reinterpret_cast<const uint32_t*>(&As[r*GLD + k0]);
                af[mi][1] = *reinterpret_cast<const uint32_t*>(&As[(r+8)*GLD + k0]);
                af[mi][2] = *reinterpret_cast<const uint32_t*>(&As[r*GLD + k0 + 8]);
                af[mi][3] = *reinterpret_cast<const uint32_t*>(&As[(r+8)*GLD + k0 + 8]);
            }
#pragma unroll
            for (int ni = 0; ni < 8; ni++) {
                int nn = wc*64 + ni*8 + grp;
                bfr[ni][0] = *reinterpret_cast<const uint32_t*>(&Bs[nn*GLD + k0]);
                bfr[ni][1] = *reinterpret_cast<const uint32_t*>(&Bs[nn*GLD + k0 + 8]);
            }
#pragma unroll
            for (int mi = 0; mi < 2; mi++)
#pragma unroll
                for (int ni = 0; ni < 8; ni++) {
                    asm volatile(
                        "mma.sync.aligned.m16n8k16.row.col.f32.bf16.bf16.f32 "
                        "{%0,%1,%2,%3}, {%4,%5,%6,%7}, {%8,%9}, {%0,%1,%2,%3};\n"
                        : "+f"(acc[mi][ni][0]), "+f"(acc[mi][ni][1]),
                          "+f"(acc[mi][ni][2]), "+f"(acc[mi][ni][3])
                        : "r"(af[mi][0]), "r"(af[mi][1]), "r"(af[mi][2]), "r"(af[mi][3]),
                          "r"(bfr[ni][0]), "r"(bfr[ni][1]));
                }
        }
        __syncthreads();
    }

    // epilogue
#pragma unroll
    for (int mi = 0; mi < 2; mi++) {
        int r0 = bm + wr*32 + mi*16 + grp;
#pragma unroll
        for (int ni = 0; ni < 8; ni++) {
            int c0 = bn + wc*64 + ni*8 + tig*2;
            if (c0 < N) {
                C[(size_t)r0*N + c0]       = acc[mi][ni][0];
                C[(size_t)(r0+8)*N + c0]   = acc[mi][ni][2];
                if (c0 + 1 < N) {
                    C[(size_t)r0*N + c0+1]     = acc[mi][ni][1];
                    C[(size_t)(r0+8)*N + c0+1] = acc[mi][ni][3];
                }
            }
        }
    }
}

// ---------------- causal depthwise conv (K=4) + SiLU ----------------
__global__ void k_conv(const float* __restrict__ conv_w, const float* __restrict__ conv_b) {
    int i = blockIdx.x*256 + threadIdx.x;
    if (i >= ROWS*DINNER) return;
    int d   = i & (DINNER-1);
    int row = i >> 11;            // DINNER = 2048
    int t   = row & (LL-1);
    int b   = row >> 11;          // LL = 2048
    float4 w = *reinterpret_cast<const float4*>(conv_w + d*4);
    float wk[4] = {w.x, w.y, w.z, w.w};
    float acc = conv_b[d];
#pragma unroll
    for (int k = 0; k < 4; k++) {
        int tp = t - 3 + k;
        if (tp >= 0)
            acc += wk[k] * g_xz[((size_t)(b*LL + tp))*(2*DINNER) + d];
    }
    float s = acc * (1.f/(1.f + expf(-acc)));   // silu
    g_xc[i]   = s;
    g_xcbf[i] = __float2bfloat16(s);
}

// extract dt_rank columns of proj -> bf16
__global__ void k_dtr() {
    int i = blockIdx.x*256 + threadIdx.x;
    if (i >= ROWS*DTRANK) return;
    int r = i >> 6, c = i & 63;
    g_dtrbf[i] = __float2bfloat16(g_proj[(size_t)r*NPROJ + c]);
}

// dt = softplus(dt_raw + b_dt), in place
__global__ void k_softplus(const float* __restrict__ b_dt) {
    int i = blockIdx.x*256 + threadIdx.x;
    if (i >= ROWS*DINNER) return;
    float v = g_dt[i] + b_dt[i & (DINNER-1)];
    g_dt[i] = (v > 20.f) ? v : log1pf(expf(v));
}

// ---------------- chunked selective scan ----------------
// Pass A: local scan with h0=0; writes y_local, h_end per chunk, and sum(dt) per chunk
__global__ __launch_bounds__(256)
void k_scanA(const float* __restrict__ A_log) {
    __shared__ float sBC[LC][32];      // per-t B[16] then C[16]
    const int c = blockIdx.x;          // chunk
    const int b = blockIdx.z;          // batch
    const int d = blockIdx.y*256 + threadIdx.x;
    const int brow = b*LL + c*LC;

    for (int i = threadIdx.x; i < LC*32; i += 256) {
        int tt = i >> 5, j = i & 31;
        sBC[tt][j] = g_proj[(size_t)(brow + tt)*NPROJ + DTRANK + j];
    }
    __syncthreads();

    float a[DSTATE], h[DSTATE];
#pragma unroll
    for (int n = 0; n < DSTATE; n++) { a[n] = -expf(A_log[d*DSTATE + n]); h[n] = 0.f; }

    float s = 0.f;
    const size_t base = (size_t)brow*DINNER + d;
    for (int tt = 0; tt < LC; tt++) {
        size_t off = base + (size_t)tt*DINNER;
        float u  = g_xc[off];
        float dt = g_dt[off];
        float du = dt*u;
        float x2 = dt*L2E;
        float y = 0.f;
#pragma unroll
        for (int n = 0; n < DSTATE; n++) {
            float e = exp2f(x2*a[n]);
            h[n] = e*h[n] + du*sBC[tt][n];
            y += h[n]*sBC[tt][16 + n];
        }
        g_ylocal[off] = y;
        s += dt;
    }
    size_t hb = ((size_t)((b*DINNER + d)*NCHUNK + c))*DSTATE;
#pragma unroll
    for (int n = 0; n < DSTATE; n++) g_hend[hb + n] = h[n];
    g_dtsum[(size_t)(b*DINNER + d)*NCHUNK + c] = s;
}

// Pass B: 16-step boundary scan; h_in[chunk] = state entering each chunk
__global__ void k_bound(const float* __restrict__ A_log) {
    int gid = blockIdx.x*256 + threadIdx.x;
    if (gid >= BB*DINNER*DSTATE) return;
    int n = gid & 15;
    int d = (gid >> 4) & (DINNER-1);
    int b = gid >> 15;
    float a = -expf(A_log[d*DSTATE + n]);
    float h = 0.f;
    size_t cb = (size_t)(b*DINNER + d)*NCHUNK;
    for (int c = 0; c < NCHUNK; c++) {
        g_hin[(cb + c)*DSTATE + n] = h;
        float s = g_dtsum[cb + c];
        h = h*exp2f(a*s*L2E) + g_hend[(cb + c)*DSTATE + n];
    }
}

// Pass C: correction y += C . (h_in * exp(A*cumdt)) fused with (y + u*D)*silu(z) -> bf16
__global__ __launch_bounds__(256)
void k_scanC(const float* __restrict__ A_log, const float* __restrict__ Dw) {
    __shared__ float sC[LC][DSTATE];
    const int c = blockIdx.x;
    const int b = blockIdx.z;
    const int d = blockIdx.y*256 + threadIdx.x;
    const int brow = b*LL + c*LC;

    for (int i = threadIdx.x; i < LC*DSTATE; i += 256) {
        int tt = i >> 4, j = i & 15;
        sC[tt][j] = g_proj[(size_t)(brow + tt)*NPROJ + DTRANK + DSTATE + j];
    }
    __syncthreads();

    float a[DSTATE], hi[DSTATE];
    size_t hb = ((size_t)((b*DINNER + d)*NCHUNK + c))*DSTATE;
#pragma unroll
    for (int n = 0; n < DSTATE; n++) {
        a[n]  = -expf(A_log[d*DSTATE + n]);
        hi[n] = g_hin[hb + n];
    }
    float Dd = Dw[d];
    float s = 0.f;
    const size_t base = (size_t)brow*DINNER + d;
    for (int tt = 0; tt < LC; tt++) {
        size_t off = base + (size_t)tt*DINNER;
        float dt = g_dt[off];
        s += dt;
        float se = s*L2E;
        float corr = 0.f;
#pragma unroll
        for (int n = 0; n < DSTATE; n++)
            corr += sC[tt][n]*hi[n]*exp2f(se*a[n]);
        float u = g_xc[off];
        float y = g_ylocal[off] + corr + u*Dd;
        float z = g_xz[(size_t)(brow + tt)*(2*DINNER) + DINNER + d];
        float g = z*(1.f/(1.f + expf(-z)));
        g_ybf[off] = __float2bfloat16(y*g);
    }
}

// ---------------- residual + RMSNorm ----------------
__global__ __launch_bounds__(256)
void k_norm(const float* __restrict__ x, const float* __restrict__ nw,
            float* __restrict__ out) {
    const int row = blockIdx.x;
    const int tid = threadIdx.x;
    float h[4];
    float ss = 0.f;
#pragma unroll
    for (int i = 0; i < 4; i++) {
        int cidx = tid + i*256;
        float v = g_out[(size_t)row*DMODEL + cidx] + x[(size_t)row*DMODEL + cidx];
        h[i] = v; ss += v*v;
    }
    __shared__ float red[8];
#pragma unroll
    for (int o = 16; o > 0; o >>= 1) ss += __shfl_xor_sync(0xffffffff, ss, o);
    if ((tid & 31) == 0) red[tid >> 5] = ss;
    __syncthreads();
    float tot = 0.f;
#pragma unroll
    for (int w = 0; w < 8; w++) tot += red[w];
    float scale = rsqrtf(tot*(1.f/DMODEL) + 1e-5f);
#pragma unroll
    for (int i = 0; i < 4; i++) {
        int cidx = tid + i*256;
        out[(size_t)row*DMODEL + cidx] = h[i]*scale*nw[cidx];
    }
}

// ---------------- launch ----------------
extern "C" void kernel_launch(void* const* d_in, const int* in_sizes, int n_in,
                              void* d_out, int out_size)
{
    const float* x      = (const float*)d_in[0];
    const float* W_in   = (const float*)d_in[1];
    const float* conv_w = (const float*)d_in[2];
    const float* conv_b = (const float*)d_in[3];
    const float* W_xproj= (const float*)d_in[4];
    const float* W_dt   = (const float*)d_in[5];
    const float* b_dt   = (const float*)d_in[6];
    const float* A_log  = (const float*)d_in[7];
    const float* Dw     = (const float*)d_in[8];
    const float* W_out  = (const float*)d_in[9];
    const float* norm_w = (const float*)d_in[10];
    float* out = (float*)d_out;

    void *p_xbf, *p_Winbf, *p_xz, *p_xcbf, *p_Wxpbf, *p_proj,
         *p_dtrbf, *p_Wdtbf, *p_dt, *p_ybf, *p_Woutbf, *p_out;
    cudaGetSymbolAddress(&p_xbf,    g_xbf);
    cudaGetSymbolAddress(&p_Winbf,  g_Winbf);
    cudaGetSymbolAddress(&p_xz,     g_xz);
    cudaGetSymbolAddress(&p_xcbf,   g_xcbf);
    cudaGetSymbolAddress(&p_Wxpbf,  g_Wxpbf);
    cudaGetSymbolAddress(&p_proj,   g_proj);
    cudaGetSymbolAddress(&p_dtrbf,  g_dtrbf);
    cudaGetSymbolAddress(&p_Wdtbf,  g_Wdtbf);
    cudaGetSymbolAddress(&p_dt,     g_dt);
    cudaGetSymbolAddress(&p_ybf,    g_ybf);
    cudaGetSymbolAddress(&p_Woutbf, g_Woutbf);
    cudaGetSymbolAddress(&p_out,    g_out);

    // fp32 -> bf16 conversions (x and weights)
    k_f2b<<<1024, 256>>>(x,      (__nv_bfloat16*)p_xbf,    ROWS*DMODEL);
    k_f2b<<<1024, 256>>>(W_in,   (__nv_bfloat16*)p_Winbf,  DMODEL*2*DINNER);
    k_f2b<<<256,  256>>>(W_xproj,(__nv_bfloat16*)p_Wxpbf,  DINNER*NPROJ);
    k_f2b<<<256,  256>>>(W_dt,   (__nv_bfloat16*)p_Wdtbf,  DTRANK*DINNER);
    k_f2b<<<1024, 256>>>(W_out,  (__nv_bfloat16*)p_Woutbf, DINNER*DMODEL);

    // GEMM1: xz = x @ W_in   [4096,4096] = [4096,1024]x[1024,4096]
    k_gemm<<<dim3(2*DINNER/GBN, ROWS/GBM), 256>>>(
        (const __nv_bfloat16*)p_xbf, (const __nv_bfloat16*)p_Winbf,
        (float*)p_xz, ROWS, 2*DINNER, DMODEL);

    // conv + silu
    k_conv<<<(ROWS*DINNER + 255)/256, 256>>>(conv_w, conv_b);

    // GEMM2: proj = xc @ W_xproj   [4096,96], K=2048
    k_gemm<<<dim3(1, ROWS/GBM), 256>>>(
        (const __nv_bfloat16*)p_xcbf, (const __nv_bfloat16*)p_Wxpbf,
        (float*)p_proj, ROWS, NPROJ, DINNER);

    k_dtr<<<(ROWS*DTRANK + 255)/256, 256>>>();

    // GEMM2b: dt_raw = dt_r @ W_dt   [4096,2048], K=64
    k_gemm<<<dim3(DINNER/GBN, ROWS/GBM), 256>>>(
        (const __nv_bfloat16*)p_dtrbf, (const __nv_bfloat16*)p_Wdtbf,
        (float*)p_dt, ROWS, DINNER, DTRANK);

    k_softplus<<<(ROWS*DINNER + 255)/256, 256>>>(b_dt);

    // chunked selective scan
    k_scanA<<<dim3(NCHUNK, DINNER/256, BB), 256>>>(A_log);
    k_bound<<<(BB*DINNER*DSTATE + 255)/256, 256>>>(A_log);
    k_scanC<<<dim3(NCHUNK, DINNER/256, BB), 256>>>(A_log, Dw);

    // GEMM3: out = y @ W_out   [4096,1024], K=2048
    k_gemm<<<dim3(DMODEL/GBN, ROWS/GBM), 256>>>(
        (const __nv_bfloat16*)p_ybf, (const __nv_bfloat16*)p_Woutbf,
        (float*)p_out, ROWS, DMODEL, DINNER);

    // residual + RMSNorm -> final output
    k_norm<<<ROWS, 256>>>(x, norm_w, out);
}

// round 14
// speedup vs baseline: 1.3619x; 1.3619x over previous
#include <cuda_runtime.h>
#include <cuda_bf16.h>
#include <stdint.h>
#include <math.h>

// ---------------- problem constants ----------------
#define DMODEL 1024
#define DINNER 2048
#define DSTATE 16
#define DCONV  4
#define DTRANK 64
#define BB     2
#define LL     2048
#define ROWS   (BB*LL)            // 4096
#define NCHUNK 16
#define LC     (LL/NCHUNK)        // 128
#define L2E    1.4426950408889634f
#define NPROJ  (DTRANK + 2*DSTATE) // 96

// ---------------- scratch ----------------
__device__ __nv_bfloat16 g_xbf   [ROWS*DMODEL];
__device__ __nv_bfloat16 g_WinT  [(size_t)2*DINNER*DMODEL];   // [4096,1024]
__device__ __nv_bfloat16 g_xz    [(size_t)ROWS*2*DINNER];     // bf16 now; xs [0,2048), z [2048,4096)
__device__ float         g_xc    [(size_t)ROWS*DINNER];
__device__ __nv_bfloat16 g_xcbf  [(size_t)ROWS*DINNER];
__device__ __nv_bfloat16 g_WxpT  [NPROJ*DINNER];              // [96,2048]
__device__ float         g_proj  [(size_t)ROWS*NPROJ];
__device__ __nv_bfloat16 g_dtrbf [(size_t)ROWS*DTRANK];
__device__ __nv_bfloat16 g_WdtT  [DINNER*DTRANK];             // [2048,64]
__device__ float         g_dt    [(size_t)ROWS*DINNER];
__device__ float         g_ylocal[(size_t)ROWS*DINNER];
__device__ float         g_hend  [(size_t)BB*DINNER*NCHUNK*DSTATE];
__device__ float         g_hin   [(size_t)BB*DINNER*NCHUNK*DSTATE];
__device__ float         g_dtsum [(size_t)BB*DINNER*NCHUNK];
__device__ __nv_bfloat16 g_ybf   [(size_t)ROWS*DINNER];
__device__ __nv_bfloat16 g_WoutT [DMODEL*DINNER];             // [1024,2048]
__device__ float         g_out   [(size_t)ROWS*DMODEL];

// ---------------- helpers ----------------
__global__ void k_f2b4(const float4* __restrict__ s, __nv_bfloat162* __restrict__ d, int n4) {
    int i = blockIdx.x*256 + threadIdx.x;
    int st = gridDim.x*256;
    for (; i < n4; i += st) {
        float4 v = s[i];
        d[2*i]   = __floats2bfloat162_rn(v.x, v.y);
        d[2*i+1] = __floats2bfloat162_rn(v.z, v.w);
    }
}

// transpose + convert: S[R,C] fp32 -> D[C,R] bf16.  R,C multiples of 32.
__global__ void k_t32(const float* __restrict__ S, __nv_bfloat16* __restrict__ D, int R, int C) {
    __shared__ float tile[32][33];
    int bc = blockIdx.x*32, br = blockIdx.y*32;
    int tx = threadIdx.x, ty = threadIdx.y;   // block (32,8)
#pragma unroll
    for (int i = 0; i < 32; i += 8)
        tile[ty+i][tx] = S[(size_t)(br+ty+i)*C + bc+tx];
    __syncthreads();
#pragma unroll
    for (int i = 0; i < 32; i += 8)
        D[(size_t)(bc+ty+i)*R + br+tx] = __float2bfloat16(tile[tx][ty+i]);
}

__device__ __forceinline__ void cpasync16(void* s, const void* g) {
    uint32_t sa = (uint32_t)__cvta_generic_to_shared(s);
    asm volatile("cp.async.cg.shared.global [%0], [%1], 16;\n" :: "r"(sa), "l"(g));
}
__device__ __forceinline__ void cp_commit() { asm volatile("cp.async.commit_group;\n"); }

__device__ __forceinline__ float softplus_f(float v) {
    return (v > 20.f) ? v : log1pf(expf(v));
}

// ---------------- double-buffered bf16 mma GEMM ----------------
// C[M,N] = A[M,K] * BT[N,K]^T ; A,BT row-major along K. fp32 accum.
// EPI: 0 = fp32 store, 1 = fp32 atomicAdd (split-K), 2 = softplus(acc+bias[c]) fp32, 3 = bf16 store
#define GBM 128
#define GBN 128
#define GBK 32
#define GLD 40

template<int EPI>
__global__ __launch_bounds__(256)
void k_gemm(const __nv_bfloat16* __restrict__ A,
            const __nv_bfloat16* __restrict__ BT,
            void* __restrict__ Cv,
            int M, int N, int K, int klen,
            const float* __restrict__ bias)
{
    __shared__ __nv_bfloat16 As[2][GBM*GLD];
    __shared__ __nv_bfloat16 Bs[2][GBN*GLD];

    const int tid  = threadIdx.x;
    const int lane = tid & 31, wid = tid >> 5;
    const int wr = wid >> 1, wc = wid & 1;
    const int grp = lane >> 2, tig = lane & 3;
    const int bm = blockIdx.y * GBM, bn = blockIdx.x * GBN;
    const int kbeg = blockIdx.z * klen;
    const int NK = klen >> 5;

    float acc[2][8][4];
#pragma unroll
    for (int a = 0; a < 2; a++)
#pragma unroll
        for (int b = 0; b < 8; b++)
#pragma unroll
            for (int c = 0; c < 4; c++) acc[a][b][c] = 0.f;

    auto load_tile = [&](int kt, int buf) {
        int kbase = kbeg + kt*GBK;
#pragma unroll
        for (int it = 0; it < 2; it++) {
            int idx = tid + it*256;
            int r = idx >> 2, c8 = (idx & 3) << 3;
            cpasync16(&As[buf][r*GLD + c8], A + (size_t)(bm + r)*K + kbase + c8);
        }
#pragma unroll
        for (int it = 0; it < 2; it++) {
            int idx = tid + it*256;
            int r = idx >> 2, c8 = (idx & 3) << 3;
            int gn = bn + r; if (gn > N-1) gn = N-1;   // clamp (N=96 tail); cols >= N never stored
            cpasync16(&Bs[buf][r*GLD + c8], BT + (size_t)gn*K + kbase + c8);
        }
    };

    load_tile(0, 0);
    cp_commit();

    for (int kt = 0; kt < NK; kt++) {
        const int cur = kt & 1;
        if (kt + 1 < NK) {
            load_tile(kt + 1, cur ^ 1);
            cp_commit();
            asm volatile("cp.async.wait_group 1;\n");
        } else {
            asm volatile("cp.async.wait_group 0;\n");
        }
        __syncthreads();

#pragma unroll
        for (int ks = 0; ks < 2; ks++) {
            const int k0 = ks*16 + tig*2;
            uint32_t af[2][4], bfr[8][2];
#pragma unroll
            for (int mi = 0; mi < 2; mi++) {
                int r = wr*32 + mi*16 + grp;
                af[mi][0] = *reinterpret_cast<const uint32_t*>(&As[cur][r*GLD + k0]);
                af[mi][1] = *reinterpret_cast<const uint32_t*>(&As[cur][(r+8)*GLD + k0]);
                af[mi][2] = *reinterpret_cast<const uint32_t*>(&As[cur][r*GLD + k0 + 8]);
                af[mi][3] = *reinterpret_cast<const uint32_t*>(&As[cur][(r+8)*GLD + k0 + 8]);
            }
#pragma unroll
            for (int ni = 0; ni < 8; ni++) {
                int nn = wc*64 + ni*8 + grp;
                bfr[ni][0] = *reinterpret_cast<const uint32_t*>(&Bs[cur][nn*GLD + k0]);
                bfr[ni][1] = *reinterpret_cast<const uint32_t*>(&Bs[cur][nn*GLD + k0 + 8]);
            }
#pragma unroll
            for (int mi = 0; mi < 2; mi++)
#pragma unroll
                for (int ni = 0; ni < 8; ni++) {
                    asm volatile(
                        "mma.sync.aligned.m16n8k16.row.col.f32.bf16.bf16.f32 "
                        "{%0,%1,%2,%3}, {%4,%5,%6,%7}, {%8,%9}, {%0,%1,%2,%3};\n"
                        : "+f"(acc[mi][ni][0]), "+f"(acc[mi][ni][1]),
                          "+f"(acc[mi][ni][2]), "+f"(acc[mi][ni][3])
                        : "r"(af[mi][0]), "r"(af[mi][1]), "r"(af[mi][2]), "r"(af[mi][3]),
                          "r"(bfr[ni][0]), "r"(bfr[ni][1]));
                }
        }
        __syncthreads();
    }

    // epilogue
#pragma unroll
    for (int mi = 0; mi < 2; mi++) {
        int r0 = bm + wr*32 + mi*16 + grp;
#pragma unroll
        for (int ni = 0; ni < 8; ni++) {
            int c0 = bn + wc*64 + ni*8 + tig*2;
#pragma unroll
            for (int cc = 0; cc < 2; cc++) {
                int c = c0 + cc;
                if (c >= N) continue;
#pragma unroll
                for (int rr = 0; rr < 2; rr++) {
                    int r = r0 + rr*8;
                    float v = acc[mi][ni][rr*2 + cc];
                    size_t off = (size_t)r*N + c;
                    if (EPI == 0) {
                        ((float*)Cv)[off] = v;
                    } else if (EPI == 1) {
                        atomicAdd(((float*)Cv) + off, v);
                    } else if (EPI == 2) {
                        ((float*)Cv)[off] = softplus_f(v + bias[c]);
                    } else {
                        ((__nv_bfloat16*)Cv)[off] = __float2bfloat16(v);
                    }
                }
            }
        }
    }
}

// ---------------- causal depthwise conv (K=4) + SiLU, 4 timesteps/thread ----------------
__global__ __launch_bounds__(256)
void k_conv4(const float* __restrict__ conv_w, const float* __restrict__ conv_b) {
    int i = blockIdx.x*256 + threadIdx.x;
    if (i >= ROWS*DINNER/4) return;
    int d  = i & (DINNER-1);
    int rq = i >> 11;
    int t0 = (rq & (LL/4 - 1)) * 4;
    int b  = rq >> 9;                 // LL/4 = 512
    float4 w = *reinterpret_cast<const float4*>(conv_w + d*4);
    float wk[4] = {w.x, w.y, w.z, w.w};
    float cb = conv_b[d];
    float xv[7];
#pragma unroll
    for (int j = 0; j < 7; j++) {
        int t = t0 - 3 + j;
        xv[j] = (t >= 0) ? __bfloat162float(g_xz[((size_t)(b*LL + t))*(2*DINNER) + d]) : 0.f;
    }
#pragma unroll
    for (int q = 0; q < 4; q++) {
        float acc = cb;
#pragma unroll
        for (int k = 0; k < 4; k++) acc += wk[k]*xv[q + k];
        float s = acc * (1.f/(1.f + expf(-acc)));
        size_t off = ((size_t)(b*LL + t0 + q))*DINNER + d;
        g_xc[off]   = s;
        g_xcbf[off] = __float2bfloat16(s);
    }
}

// extract dt_rank columns of proj -> bf16
__global__ void k_dtr() {
    int i = blockIdx.x*256 + threadIdx.x;
    if (i >= ROWS*DTRANK) return;
    int r = i >> 6, c = i & 63;
    g_dtrbf[i] = __float2bfloat16(g_proj[(size_t)r*NPROJ + c]);
}

// ---------------- chunked selective scan ----------------
__global__ __launch_bounds__(256)
void k_scanA(const float* __restrict__ A_log) {
    __shared__ float sBC[LC][32];
    const int c = blockIdx.x;
    const int b = blockIdx.z;
    const int d = blockIdx.y*256 + threadIdx.x;
    const int brow = b*LL + c*LC;

    for (int i = threadIdx.x; i < LC*32; i += 256) {
        int tt = i >> 5, j = i & 31;
        sBC[tt][j] = g_proj[(size_t)(brow + tt)*NPROJ + DTRANK + j];
    }
    __syncthreads();

    float a[DSTATE], h[DSTATE];
#pragma unroll
    for (int n = 0; n < DSTATE; n++) { a[n] = -expf(A_log[d*DSTATE + n]); h[n] = 0.f; }

    float s = 0.f;
    const size_t base = (size_t)brow*DINNER + d;
    for (int tt = 0; tt < LC; tt++) {
        size_t off = base + (size_t)tt*DINNER;
        float u  = g_xc[off];
        float dt = g_dt[off];
        float du = dt*u;
        float x2 = dt*L2E;
        float y = 0.f;
#pragma unroll
        for (int n = 0; n < DSTATE; n++) {
            float e = exp2f(x2*a[n]);
            h[n] = e*h[n] + du*sBC[tt][n];
            y += h[n]*sBC[tt][16 + n];
        }
        g_ylocal[off] = y;
        s += dt;
    }
    size_t hb = ((size_t)((b*DINNER + d)*NCHUNK + c))*DSTATE;
#pragma unroll
    for (int n = 0; n < DSTATE; n++) g_hend[hb + n] = h[n];
    g_dtsum[(size_t)(b*DINNER + d)*NCHUNK + c] = s;
}

__global__ void k_bound(const float* __restrict__ A_log) {
    int gid = blockIdx.x*256 + threadIdx.x;
    if (gid >= BB*DINNER*DSTATE) return;
    int n = gid & 15;
    int d = (gid >> 4) & (DINNER-1);
    int b = gid >> 15;
    float a = -expf(A_log[d*DSTATE + n]);
    float h = 0.f;
    size_t cb = (size_t)(b*DINNER + d)*NCHUNK;
    for (int c = 0; c < NCHUNK; c++) {
        g_hin[(cb + c)*DSTATE + n] = h;
        float s = g_dtsum[cb + c];
        h = h*exp2f(a*s*L2E) + g_hend[(cb + c)*DSTATE + n];
    }
}

__global__ __launch_bounds__(256)
void k_scanC(const float* __restrict__ A_log, const float* __restrict__ Dw) {
    __shared__ float sC[LC][DSTATE];
    const int c = blockIdx.x;
    const int b = blockIdx.z;
    const int d = blockIdx.y*256 + threadIdx.x;
    const int brow = b*LL + c*LC;

    for (int i = threadIdx.x; i < LC*DSTATE; i += 256) {
        int tt = i >> 4, j = i & 15;
        sC[tt][j] = g_proj[(size_t)(brow + tt)*NPROJ + DTRANK + DSTATE + j];
    }
    __syncthreads();

    float a[DSTATE], hi[DSTATE];
    size_t hb = ((size_t)((b*DINNER + d)*NCHUNK + c))*DSTATE;
#pragma unroll
    for (int n = 0; n < DSTATE; n++) {
        a[n]  = -expf(A_log[d*DSTATE + n]);
        hi[n] = g_hin[hb + n];
    }
    float Dd = Dw[d];
    float s = 0.f;
    const size_t base = (size_t)brow*DINNER + d;
    for (int tt = 0; tt < LC; tt++) {
        size_t off = base + (size_t)tt*DINNER;
        float dt = g_dt[off];
        s += dt;
        float se = s*L2E;
        float corr = 0.f;
#pragma unroll
        for (int n = 0; n < DSTATE; n++)
            corr += sC[tt][n]*hi[n]*exp2f(se*a[n]);
        float u = g_xc[off];
        float y = g_ylocal[off] + corr + u*Dd;
        float z = __bfloat162float(g_xz[(size_t)(brow + tt)*(2*DINNER) + DINNER + d]);
        float g = z*(1.f/(1.f + expf(-z)));
        g_ybf[off] = __float2bfloat16(y*g);
    }
}

// ---------------- residual + RMSNorm ----------------
__global__ __launch_bounds__(256)
void k_norm(const float* __restrict__ x, const float* __restrict__ nw,
            float* __restrict__ out) {
    const int row = blockIdx.x;
    const int tid = threadIdx.x;
    float h[4];
    float ss = 0.f;
#pragma unroll
    for (int i = 0; i < 4; i++) {
        int cidx = tid + i*256;
        float v = g_out[(size_t)row*DMODEL + cidx] + x[(size_t)row*DMODEL + cidx];
        h[i] = v; ss += v*v;
    }
    __shared__ float red[8];
#pragma unroll
    for (int o = 16; o > 0; o >>= 1) ss += __shfl_xor_sync(0xffffffff, ss, o);
    if ((tid & 31) == 0) red[tid >> 5] = ss;
    __syncthreads();
    float tot = 0.f;
#pragma unroll
    for (int w = 0; w < 8; w++) tot += red[w];
    float scale = rsqrtf(tot*(1.f/DMODEL) + 1e-5f);
#pragma unroll
    for (int i = 0; i < 4; i++) {
        int cidx = tid + i*256;
        out[(size_t)row*DMODEL + cidx] = h[i]*scale*nw[cidx];
    }
}

// ---------------- launch ----------------
extern "C" void kernel_launch(void* const* d_in, const int* in_sizes, int n_in,
                              void* d_out, int out_size)
{
    const float* x      = (const float*)d_in[0];
    const float* W_in   = (const float*)d_in[1];
    const float* conv_w = (const float*)d_in[2];
    const float* conv_b = (const float*)d_in[3];
    const float* W_xproj= (const float*)d_in[4];
    const float* W_dt   = (const float*)d_in[5];
    const float* b_dt   = (const float*)d_in[6];
    const float* A_log  = (const float*)d_in[7];
    const float* Dw     = (const float*)d_in[8];
    const float* W_out  = (const float*)d_in[9];
    const float* norm_w = (const float*)d_in[10];
    float* out = (float*)d_out;

    void *p_xbf, *p_WinT, *p_xz, *p_xcbf, *p_WxpT, *p_proj,
         *p_dtrbf, *p_WdtT, *p_dt, *p_ybf, *p_WoutT, *p_out;
    cudaGetSymbolAddress(&p_xbf,   g_xbf);
    cudaGetSymbolAddress(&p_WinT,  g_WinT);
    cudaGetSymbolAddress(&p_xz,    g_xz);
    cudaGetSymbolAddress(&p_xcbf,  g_xcbf);
    cudaGetSymbolAddress(&p_WxpT,  g_WxpT);
    cudaGetSymbolAddress(&p_proj,  g_proj);
    cudaGetSymbolAddress(&p_dtrbf, g_dtrbf);
    cudaGetSymbolAddress(&p_WdtT,  g_WdtT);
    cudaGetSymbolAddress(&p_dt,    g_dt);
    cudaGetSymbolAddress(&p_ybf,   g_ybf);
    cudaGetSymbolAddress(&p_WoutT, g_WoutT);
    cudaGetSymbolAddress(&p_out,   g_out);

    // x -> bf16 (vectorized)
    k_f2b4<<<512, 256>>>((const float4*)x, (__nv_bfloat162*)p_xbf, ROWS*DMODEL/4);
    // weight transposes + bf16 convert: S[R,C] -> D[C,R]
    k_t32<<<dim3((2*DINNER)/32, DMODEL/32), dim3(32,8)>>>(W_in,   (__nv_bfloat16*)p_WinT,  DMODEL, 2*DINNER);
    k_t32<<<dim3(NPROJ/32,     DINNER/32), dim3(32,8)>>>(W_xproj,(__nv_bfloat16*)p_WxpT,  DINNER, NPROJ);
    k_t32<<<dim3(DINNER/32,    DTRANK/32), dim3(32,8)>>>(W_dt,   (__nv_bfloat16*)p_WdtT,  DTRANK, DINNER);
    k_t32<<<dim3(DMODEL/32,    DINNER/32), dim3(32,8)>>>(W_out,  (__nv_bfloat16*)p_WoutT, DINNER, DMODEL);

    // GEMM1: xz(bf16) = x @ W_in   [4096,4096], K=1024
    k_gemm<3><<<dim3(2*DINNER/GBN, ROWS/GBM, 1), 256>>>(
        (const __nv_bfloat16*)p_xbf, (const __nv_bfloat16*)p_WinT,
        p_xz, ROWS, 2*DINNER, DMODEL, DMODEL, nullptr);

    // conv + silu
    k_conv4<<<(ROWS*DINNER/4 + 255)/256, 256>>>(conv_w, conv_b);

    // GEMM2 (split-K 8-way, atomic): proj = xc @ W_xproj  [4096,96], K=2048
    cudaMemsetAsync(p_proj, 0, (size_t)ROWS*NPROJ*sizeof(float));
    k_gemm<1><<<dim3(1, ROWS/GBM, 8), 256>>>(
        (const __nv_bfloat16*)p_xcbf, (const __nv_bfloat16*)p_WxpT,
        p_proj, ROWS, NPROJ, DINNER, DINNER/8, nullptr);

    k_dtr<<<(ROWS*DTRANK + 255)/256, 256>>>();

    // GEMM2b (+fused bias+softplus): dt = softplus(dt_r @ W_dt + b_dt)  [4096,2048], K=64
    k_gemm<2><<<dim3(DINNER/GBN, ROWS/GBM, 1), 256>>>(
        (const __nv_bfloat16*)p_dtrbf, (const __nv_bfloat16*)p_WdtT,
        p_dt, ROWS, DINNER, DTRANK, DTRANK, b_dt);

    // chunked selective scan
    k_scanA<<<dim3(NCHUNK, DINNER/256, BB), 256>>>(A_log);
    k_bound<<<(BB*DINNER*DSTATE + 255)/256, 256>>>(A_log);
    k_scanC<<<dim3(NCHUNK, DINNER/256, BB), 256>>>(A_log, Dw);

    // GEMM3: out = y @ W_out   [4096,1024], K=2048
    k_gemm<0><<<dim3(DMODEL/GBN, ROWS/GBM, 1), 256>>>(
        (const __nv_bfloat16*)p_ybf, (const __nv_bfloat16*)p_WoutT,
        p_out, ROWS, DMODEL, DINNER, DINNER, nullptr);

    // residual + RMSNorm
    k_norm<<<ROWS, 256>>>(x, norm_w, out);
}